// round 16
// baseline (speedup 1.0000x reference)
#include <cuda_runtime.h>
#include <cuda_fp16.h>
#include <cstdint>

// S4 kernel materialization on HMMA (mma.sync m16n8k16 fp16):
//   K[h,l] = 2*Re( sum_n Cc_n z_n^l ),  z = exp(dtA), Cc = C*(z-1)/A
// l = 64q + r -> per-h GEMM D[64q][64r] = A[64x64] @ B[64x64]^T (K=64, j=2n re/im)
// Single fp16 product, fp32 accum (rel_err ~2e-4).
// R16 = R15 + full-ks fragment prefetch (b[16], no WAR serialization)
//           + head algebra (dtar = -exp(ld+la), fold dt into reciprocal).

#define Hh   1024
#define NHn  32
#define Ll   4096

__device__ __forceinline__ uint32_t pack_h2(float re, float im) {
    __half2 v = __floats2half2_rn(re, im);   // low = re (k even), high = im (k odd)
    return *(uint32_t*)&v;
}

__device__ __forceinline__ void mma16816(float* c, const uint32_t* a,
                                         uint32_t b0, uint32_t b1) {
    asm volatile(
        "mma.sync.aligned.m16n8k16.row.col.f32.f16.f16.f32 "
        "{%0,%1,%2,%3}, {%4,%5,%6,%7}, {%8,%9}, {%0,%1,%2,%3};"
        : "+f"(c[0]), "+f"(c[1]), "+f"(c[2]), "+f"(c[3])
        : "r"(a[0]), "r"(a[1]), "r"(a[2]), "r"(a[3]), "r"(b0), "r"(b1));
}

__device__ __forceinline__ void ldmx4(uint32_t* r, uint32_t addr) {
    asm volatile(
        "ldmatrix.sync.aligned.m8n8.x4.shared.b16 {%0,%1,%2,%3}, [%4];"
        : "=r"(r[0]), "=r"(r[1]), "=r"(r[2]), "=r"(r[3]) : "r"(addr));
}

// z^k = exp(k*dtar) * cis(k*dtai)
__device__ __forceinline__ float2 zpow(float k, float dtar, float dtai) {
    float er = __expf(k * dtar);
    float sn, cs;
    __sincosf(k * dtai, &sn, &cs);
    return make_float2(er * cs, er * sn);
}

__global__ __launch_bounds__(128, 7)
void s4_hmma_kernel(const float* __restrict__ Cin,        // [H, NH, 2]
                    const float* __restrict__ log_dt,     // [H]
                    const float* __restrict__ log_A_real, // [H, NH]
                    const float* __restrict__ A_imag,     // [H, NH]
                    float* __restrict__ out)              // [H, L]
{
    // 64 rows x 32 words (64 fp16) per tile, XOR swizzle: word = n ^ ((row&7)<<2)
    __shared__ uint32_t At[64 * 32];
    __shared__ uint32_t Bt[64 * 32];

    const int h    = blockIdx.x;
    const int tid  = threadIdx.x;
    const int lane = tid & 31;
    const int w    = tid >> 5;

    // ---- phase 1: direct-exp anchors + 4 chains x 8 steps per warp ----
    {
        const int n = lane;

        float ld   = log_dt[h];
        float dt   = __expf(ld);
        float dtar = -__expf(ld + log_A_real[h * NHn + n]);   // Re(dtA)
        float dtai = -A_imag[h * NHn + n] * dt;               // Im(dtA)

        // independent anchors (no serial squaring)
        float2 z   = zpow(1.0f, dtar, dtai);                       // z
        float2 z64 = zpow(64.0f, dtar, dtai);                      // z^64
        float2 p0  = zpow((float)(16 * w),         dtar, dtai);    // z^(16w)
        float2 p1  = zpow((float)(16 * w + 8),     dtar, dtai);    // z^(16w+8)
        float2 a0  = zpow((float)(1024 * w),       dtar, dtai);    // z^(1024w)
        float2 a1  = zpow((float)(1024 * w + 512), dtar, dtai);    // z^(1024w+512)

        // Cc = C * (z-1)/A = C * (z-1) * dt * conj(dtA)/|dtA|^2
        float nr = z.x - 1.0f, ni = z.y;
        float inv = __fdividef(dt, dtar * dtar + dtai * dtai);
        float fr = (nr * dtar + ni * dtai) * inv;
        float fi = (ni * dtar - nr * dtai) * inv;
        float c0 = Cin[(h * NHn + n) * 2 + 0];
        float c1 = Cin[(h * NHn + n) * 2 + 1];
        float ccr = c0 * fr - c1 * fi;
        float cci = c0 * fi + c1 * fr;

        // B chains conjugated with folded 2/-2: s_r = 2*conj(Cc z^r), step conj(z)
        float u0r = ccr * p0.x - cci * p0.y;
        float u0i = ccr * p0.y + cci * p0.x;
        float s0r = 2.0f * u0r, s0i = -2.0f * u0i;
        float u1r = ccr * p1.x - cci * p1.y;
        float u1i = ccr * p1.y + cci * p1.x;
        float s1r = 2.0f * u1r, s1i = -2.0f * u1i;
        const float bzr = z.x, bzi = -z.y;           // conj(z)

        // A chains: t = z^(64q), step z^64
        float t0r = a0.x, t0i = a0.y;
        float t1r = a1.x, t1i = a1.y;

        const int base = w * 512;                    // w*16 rows * 32 words

        #pragma unroll
        for (int i = 0; i < 8; i++) {
            int wo0 = base + i * 32 + (n ^ (i << 2));    // row 16w+i   (&7 == i)
            int wo1 = wo0 + 256;                         // row 16w+8+i
            Bt[wo0] = pack_h2(s0r, s0i);
            Bt[wo1] = pack_h2(s1r, s1i);
            At[wo0] = pack_h2(t0r, t0i);
            At[wo1] = pack_h2(t1r, t1i);

            float t;
            t = s0r * bzr - s0i * bzi;      s0i = s0r * bzi + s0i * bzr;      s0r = t;
            t = s1r * bzr - s1i * bzi;      s1i = s1r * bzi + s1i * bzr;      s1r = t;
            t = t0r * z64.x - t0i * z64.y;  t0i = t0r * z64.y + t0i * z64.x;  t0r = t;
            t = t1r * z64.x - t1i * z64.y;  t1i = t1r * z64.y + t1i * z64.x;  t1r = t;
        }
    }
    __syncthreads();

    // ---- phase 2: MMA, all 5 ldmatrix of a ks-chunk issued up front ----
    const int lane8 = lane & 7;
    const int g     = lane >> 3;          // ldmatrix matrix-group 0..3
    const uint32_t swx = (uint32_t)lane8 << 2;

    uint32_t aBase = (uint32_t)__cvta_generic_to_shared(At);
    uint32_t bBase = (uint32_t)__cvta_generic_to_shared(Bt);

    const uint32_t aRow  = (uint32_t)(w * 16 + ((g & 1) << 3) + lane8);
    const uint32_t aOff0 = (aRow << 5) << 2;
    const uint32_t aKsel = (uint32_t)((g >> 1) << 2);

    const uint32_t bKsel = (uint32_t)((g & 1) << 2);
    uint32_t bOff0[4];
    #pragma unroll
    for (int p = 0; p < 4; p++) {
        uint32_t nt0 = (uint32_t)(2 * p + (g >> 1));
        uint32_t row = (nt0 << 3) + (uint32_t)lane8;
        bOff0[p] = (row << 5) << 2;
    }

    float acc[8][4];
    #pragma unroll
    for (int nt = 0; nt < 8; nt++)
        #pragma unroll
        for (int i = 0; i < 4; i++) acc[nt][i] = 0.0f;

    #pragma unroll
    for (int ks = 0; ks < 4; ks++) {
        uint32_t aw_  = (uint32_t)(ks * 8) + aKsel;
        uint32_t aoff = aOff0 + ((aw_ ^ swx) << 2);
        uint32_t wc   = (uint32_t)(ks * 8) + bKsel;
        uint32_t wcs  = (wc ^ swx) << 2;

        uint32_t a[4], b[16];
        ldmx4(a, aBase + aoff);
        ldmx4(&b[0],  bBase + bOff0[0] + wcs);
        ldmx4(&b[4],  bBase + bOff0[1] + wcs);
        ldmx4(&b[8],  bBase + bOff0[2] + wcs);
        ldmx4(&b[12], bBase + bOff0[3] + wcs);

        #pragma unroll
        for (int nt = 0; nt < 8; nt++)
            mma16816(acc[nt], a, b[nt * 2], b[nt * 2 + 1]);
    }

    // ---- epilogue: D(q, r) -> out[h, 64q + r] ----
    const int lane4 = lane >> 2;
    const int kq    = lane & 3;
    const int q0 = w * 16 + lane4, q1 = q0 + 8;
    const int cb = kq * 2;
    float* o = out + (size_t)h * Ll;
    #pragma unroll
    for (int nt = 0; nt < 8; nt++) {
        int c = nt * 8 + cb;
        *(float2*)&o[q0 * 64 + c] = make_float2(acc[nt][0], acc[nt][1]);
        *(float2*)&o[q1 * 64 + c] = make_float2(acc[nt][2], acc[nt][3]);
    }
}

extern "C" void kernel_launch(void* const* d_in, const int* in_sizes, int n_in,
                              void* d_out, int out_size)
{
    const float* C          = (const float*)d_in[0];   // [H, NH, 2]
    const float* log_dt     = (const float*)d_in[1];   // [H]
    const float* log_A_real = (const float*)d_in[2];   // [H, NH]
    const float* A_imag     = (const float*)d_in[3];   // [H, NH]
    float* out              = (float*)d_out;           // [H, L]

    s4_hmma_kernel<<<Hh, 128>>>(C, log_dt, log_A_real, A_imag, out);
}